// round 15
// baseline (speedup 1.0000x reference)
#include <cuda_runtime.h>

// LUT-tree conv: B=8, C=64, H=W=32, O=32, Q=8, K=3.
// R13: revert tanh (TANH is slow-rate on sm_103a) -> ex2+rcp sigmoid;
//      4 px/thread at 64-thread blocks: grid stays 1024 (balanced single wave),
//      coeff-LDS + overhead amortized over 4 px (-36% dynamic instr, 2x ILP),
//      launch_bounds(64,9) -> 113-reg budget, no spills.
//      Eval core otherwise the R9 winner (Möbius-Horner + folding, rolling rows).

#define STRIDE 36
#define HROWS  10                    // 8 output rows + 2 halo
#define PLANE  (HROWS * STRIDE)      // 360 floats per channel plane

__device__ __forceinline__ float fsig(float x) {
    // sigmoid via ex2.approx + rcp.approx (~1e-6 rel err, 2 MUFU)
    float e, r;
    asm("ex2.approx.f32 %0, %1;" : "=f"(e) : "f"(x * -1.4426950408889634f));
    asm("rcp.approx.f32 %0, %1;" : "=f"(r) : "f"(1.0f + e));
    return r;
}

// Horner eval of multilinear interp with Möbius coeffs: 15 FMA, zero FADD.
__device__ __forceinline__ float lut4m(const float c[16],
                                       float x0, float x1, float x2, float x3) {
    float u0 = fmaf(x0, c[1],  c[0]);
    float u1 = fmaf(x0, c[3],  c[2]);
    float u2 = fmaf(x0, c[5],  c[4]);
    float u3 = fmaf(x0, c[7],  c[6]);
    float u4 = fmaf(x0, c[9],  c[8]);
    float u5 = fmaf(x0, c[11], c[10]);
    float u6 = fmaf(x0, c[13], c[12]);
    float u7 = fmaf(x0, c[15], c[14]);
    float v0 = fmaf(x1, u1, u0);
    float v1 = fmaf(x1, u3, u2);
    float v2 = fmaf(x1, u5, u4);
    float v3 = fmaf(x1, u7, u6);
    float w0 = fmaf(x2, v1, v0);
    float w1 = fmaf(x2, v3, v2);
    return fmaf(x3, w1, w0);
}

// 2-input folded LUT: 3 FMA.
__device__ __forceinline__ float lut2m(float4 c, float x0, float x1) {
    return fmaf(x1, fmaf(x0, c.w, c.z), fmaf(x0, c.y, c.x));
}

// Coeff fetch: 4x LDS.128 broadcast (uniform address).
__device__ __forceinline__ void ldc16(float c[16], const float* Wc, int lut) {
    const float4* p = reinterpret_cast<const float4*>(Wc + lut * 16);
    #pragma unroll
    for (int j = 0; j < 4; j++) {
        float4 t = p[j];
        c[4*j+0] = t.x; c[4*j+1] = t.y; c[4*j+2] = t.z; c[4*j+3] = t.w;
    }
}

__global__ __launch_bounds__(64, 9) void lut_tree_kernel(
    const float* __restrict__ x,
    const float* __restrict__ w0, const float* __restrict__ w1,
    const float* __restrict__ w2, const float* __restrict__ w3,
    const int* __restrict__ ci, float* __restrict__ out)
{
    __shared__ __align__(16) float S[8 * PLANE];   // sigmoided channels + halo
    __shared__ __align__(16) float Wc[26 * 16];    // Möbius coeffs (some folded)

    const int o   = blockIdx.x;          // 0..31
    const int b   = blockIdx.y;          // 0..7
    const int h0  = blockIdx.z << 3;     // 0,8,16,24
    const int tid = threadIdx.x;         // 0..63

    // ---- Stage + Möbius-transform (+constant-fold) weights; thread t = LUT t ----
    if (tid < 26) {
        const float* src;
        if (tid < 18)      src = w0 + o * 288 + tid * 16;
        else if (tid < 23) src = w1 + o * 80  + (tid - 18) * 16;
        else if (tid < 25) src = w2 + o * 32  + (tid - 23) * 16;
        else               src = w3 + o * 16;
        float t16[16];
        #pragma unroll
        for (int i = 0; i < 16; i++) t16[i] = src[i];
        #pragma unroll
        for (int d = 0; d < 4; d++) {            // finite-difference transform
            const int s = 1 << d;
            #pragma unroll
            for (int j = 0; j < 16; j++)
                if (j & s) t16[j] -= t16[j ^ s];
        }
        // fold constant-0.5 inputs: LUT22 & LUT25 fold dims 3,2; LUT24 dims 3,2,1.
        const int nfold = (tid == 22 || tid == 25) ? 2 : (tid == 24 ? 3 : 0);
        for (int d = 3; d > 3 - nfold; d--) {
            const int s = 1 << d;
            for (int j = 0; j < s; j++) t16[j] += 0.5f * t16[j + s];
        }
        #pragma unroll
        for (int i = 0; i < 16; i++) Wc[tid * 16 + i] = t16[i];
    }

    // ---- Init planes to 0.5 (covers conv zero-pad halo) ----
    {
        float4 hv = make_float4(0.5f, 0.5f, 0.5f, 0.5f);
        float4* S4 = reinterpret_cast<float4*>(S);
        for (int i = tid; i < 8 * PLANE / 4; i += 64) S4[i] = hv;
    }
    __syncthreads();

    // ---- Fill interior: sigmoid of selected channels (320 = 5*64, no guard) ----
    #pragma unroll
    for (int q = 0; q < 8; q++) {
        const int ch = ci[o * 8 + q];
        const float* xc = x + ((size_t)(b * 64 + ch)) * 1024;
        #pragma unroll
        for (int i0 = 0; i0 < HROWS * 32; i0 += 64) {
            const int i = i0 + tid;
            const int r = i >> 5, w = i & 31;
            const int hin = h0 - 1 + r;
            if (hin >= 0 && hin < 32)
                S[q * PLANE + r * STRIDE + 1 + w] = fsig(xc[hin * 32 + w]);
        }
    }
    __syncthreads();

    // ---- Eval: thread -> output row ty (of 8), 4 consecutive cols ----
    const int ty = tid >> 3;              // 0..7
    const int wb = (tid & 7) << 2;        // 0,4,...,28 (16B aligned)

    // Rolling feature-row pair: va = row rA, vb = row rA+1 (rA = 4l/3).
    // 6 floats per row serve all 4 pixels (cols wb-1+kw .. : indices kw..kw+3).
    float va[6], vb[6];
    #define LOADROW(dst, R) do {                                               \
        const float* p_ = S + ((R) / 3) * PLANE + (ty + (R) % 3) * STRIDE + wb;\
        float4 f0_ = *(const float4*)p_;                                       \
        float2 f1_ = *(const float2*)(p_ + 4);                                 \
        dst[0] = f0_.x; dst[1] = f0_.y; dst[2] = f0_.z; dst[3] = f0_.w;        \
        dst[4] = f1_.x; dst[5] = f1_.y;                                        \
    } while (0)

    float ing[4][4];   // current level-1 group inputs [k][pixel]
    float h1s[4][5];   // sigmoided level-1 outputs [pixel][g]

    LOADROW(va, 0);
    LOADROW(vb, 1);

    #pragma unroll
    for (int l = 0; l < 18; l++) {
        const int k = l & 3;
        const int g = l >> 2;
        const int rA = (4 * l) / 3;
        float c[16]; ldc16(c, Wc, l);
        #pragma unroll
        for (int p = 0; p < 4; p++) {
            float xi[4];
            #pragma unroll
            for (int i = 0; i < 4; i++) {
                const int j  = 4 * l + i;     // compile-time
                const int rr = j / 3;
                const int kw = j % 3;
                xi[i] = (rr == rA) ? va[kw + p] : vb[kw + p];
            }
            ing[k][p] = fsig(lut4m(c, xi[0], xi[1], xi[2], xi[3]));
        }
        // level-1 reduction when a group completes
        if (k == 3) {                        // groups 0..3 (full LUT4)
            float cg[16]; ldc16(cg, Wc, 18 + g);
            #pragma unroll
            for (int p = 0; p < 4; p++)
                h1s[p][g] = fsig(lut4m(cg, ing[0][p], ing[1][p], ing[2][p], ing[3][p]));
        }
        if (l == 17) {                       // group 4: folded 2-input LUT
            float4 c4 = *reinterpret_cast<const float4*>(Wc + 22 * 16);
            #pragma unroll
            for (int p = 0; p < 4; p++)
                h1s[p][4] = fsig(lut2m(c4, ing[0][p], ing[1][p]));
        }
        // advance rolling rows
        if (l < 17) {
            const int rN = (4 * (l + 1)) / 3;
            if (rN == rA + 1) {
                #pragma unroll
                for (int i = 0; i < 6; i++) va[i] = vb[i];
                LOADROW(vb, rN + 1);
            } else {
                LOADROW(va, rN);
                LOADROW(vb, rN + 1);
            }
        }
    }
    #undef LOADROW

    // Level 2: LUT23 full; LUT24 folded to linear (1 FMA).
    float h2s[4][2];
    {
        float c[16]; ldc16(c, Wc, 23);
        #pragma unroll
        for (int p = 0; p < 4; p++)
            h2s[p][0] = fsig(lut4m(c, h1s[p][0], h1s[p][1], h1s[p][2], h1s[p][3]));
    }
    {
        float2 c2 = *reinterpret_cast<const float2*>(Wc + 24 * 16);
        #pragma unroll
        for (int p = 0; p < 4; p++)
            h2s[p][1] = fsig(fmaf(h1s[p][4], c2.y, c2.x));
    }

    // Level 3 (no sigmoid): folded bilinear (3 FMA per pixel).
    float4 ov;
    {
        float4 c4 = *reinterpret_cast<const float4*>(Wc + 25 * 16);
        ov.x = lut2m(c4, h2s[0][0], h2s[0][1]);
        ov.y = lut2m(c4, h2s[1][0], h2s[1][1]);
        ov.z = lut2m(c4, h2s[2][0], h2s[2][1]);
        ov.w = lut2m(c4, h2s[3][0], h2s[3][1]);
    }

    const int h = h0 + ty;
    *reinterpret_cast<float4*>(&out[(((b * 32 + o) * 32 + h) * 32) + wb]) = ov;
}

extern "C" void kernel_launch(void* const* d_in, const int* in_sizes, int n_in,
                              void* d_out, int out_size) {
    const float* x  = (const float*)d_in[0];
    const float* w0 = (const float*)d_in[1];
    const float* w1 = (const float*)d_in[2];
    const float* w2 = (const float*)d_in[3];
    const float* w3 = (const float*)d_in[4];
    const int*   ci = (const int*)d_in[5];

    dim3 grid(32, 8, 4);   // (O, B, H-quarter) — 1024 blocks, single balanced wave
    lut_tree_kernel<<<grid, 64>>>(x, w0, w1, w2, w3, ci, (float*)d_out);
}